// round 2
// baseline (speedup 1.0000x reference)
#include <cuda_runtime.h>
#include <cstdint>

// Problem constants
// u_t    [16,3,32,32]  f32   d_in[0]
// h_prev [16,9,128,64,64] f32 d_in[1]
// action [16,2] int32         d_in[2]
// W_u    [128,3,3,3] f32      d_in[3]
// W_h    [128,128,3,3] f32    d_in[4]
// out    [16,9,128,64,64] f32
#define WORLD 64
#define WIN   32
#define CC    128
#define BB    16
#define VV    9
#define CI_CHUNK 8

// Scratch (device globals; allocation inside kernel_launch is forbidden)
__device__ float g_Wt[9 * 128 * 128];              // [tap][ci][co]
__device__ float g_uconv[16 * 128 * 32 * 32];      // [b][co][y][x]

// ---------- packed f32x2 helpers ----------
__device__ __forceinline__ unsigned long long bcast2(float v) {
    unsigned long long r;
    unsigned int u = __float_as_uint(v);
    asm("mov.b64 %0, {%1, %2};" : "=l"(r) : "r"(u), "r"(u));
    return r;
}
__device__ __forceinline__ void ffma2(unsigned long long& a,
                                      unsigned long long w,
                                      unsigned long long b) {
    asm("fma.rn.f32x2 %0, %1, %2, %0;" : "+l"(a) : "l"(w), "l"(b));
}

// ---------- W_h transpose: [co][ci][tap] -> [tap][ci][co] ----------
__global__ void transpose_wh_kernel(const float* __restrict__ W_h) {
    int idx = blockIdx.x * blockDim.x + threadIdx.x;
    if (idx >= 9 * 128 * 128) return;
    int co  = idx & 127;
    int ci  = (idx >> 7) & 127;
    int tap = idx >> 14;
    g_Wt[idx] = W_h[(co * 128 + ci) * 9 + tap];
}

// ---------- encoder: circular conv u_t * W_u -> g_uconv ----------
__global__ void encoder_kernel(const float* __restrict__ u_t,
                               const float* __restrict__ W_u) {
    int co = blockIdx.x;
    int b  = blockIdx.y;
    __shared__ float us[3 * 32 * 32];
    __shared__ float ws[27];
    int tid = threadIdx.x;
    const float* up = u_t + (size_t)b * 3 * 1024;
    for (int e = tid; e < 3072; e += 256) us[e] = up[e];
    if (tid < 27) ws[tid] = W_u[co * 27 + tid];
    __syncthreads();

    int y  = (tid * 4) >> 5;
    int x0 = (tid * 4) & 31;
    float acc[4] = {0.f, 0.f, 0.f, 0.f};
#pragma unroll
    for (int ci = 0; ci < 3; ++ci)
#pragma unroll
        for (int ky = 0; ky < 3; ++ky) {
            int yy = (y + ky - 1 + 32) & 31;
#pragma unroll
            for (int kx = 0; kx < 3; ++kx) {
                float w = ws[ci * 9 + ky * 3 + kx];
#pragma unroll
                for (int k = 0; k < 4; ++k) {
                    int xx = (x0 + k + kx - 1 + 32) & 31;
                    acc[k] = fmaf(w, us[ci * 1024 + yy * 32 + xx], acc[k]);
                }
            }
        }
    float4 r = {acc[0], acc[1], acc[2], acc[3]};
    *(float4*)&g_uconv[((size_t)(b * 128 + co) * 32 + y) * 32 + x0] = r;
}

// ---------- main recurrent conv ----------
// Block: one (b, v), 2 output rows. Threads 256: tid = cg*32 + pxg;
// cg (0..7) selects 16 output channels; pxg -> (row_local, x0=4*xg).
// Per thread: 8 co-pairs x 4 px f32x2 accumulators.
__global__ __launch_bounds__(256)
void fernn_main_kernel(const float* __restrict__ h_prev,
                       const int* __restrict__ action,
                       float* __restrict__ out) {
    __shared__ float w_s[CI_CHUNK][9][128];   // [ci][tap][co]
    __shared__ float in_s[CI_CHUNK][4][72];   // [ci][ry][xx], xx-1 = pixel x offset

    int rt = blockIdx.x;   // 0..31 row-pair tile
    int v  = blockIdx.y;   // 0..8
    int b  = blockIdx.z;   // 0..15
    int row0 = rt * 2;

    int tid = threadIdx.x;
    int cg  = tid >> 5;          // 0..7
    int pxg = tid & 31;
    int rl  = pxg >> 4;          // 0..1
    int x0  = (pxg & 15) * 4;    // 0..60

    int ax = action[b * 2 + 0];
    int ay = action[b * 2 + 1];
    int vx = v / 3 - 1;
    int vy = v % 3 - 1;
    // reference (code, not comment!): input = h_prev[b,v,(ci-vy)%C,(y+ky-1+ay-vx)%H,(x+kx-1+ax)%W]
    int Sy = ay - vx;
    int Sx = ax;

    const float* hp = h_prev + (size_t)(b * VV + v) * CC * WORLD * WORLD;

    unsigned long long acc[8][4];
#pragma unroll
    for (int j = 0; j < 8; ++j)
#pragma unroll
        for (int k = 0; k < 4; ++k) acc[j][k] = 0ull;

#pragma unroll 1
    for (int chunk = 0; chunk < CC / CI_CHUNK; ++chunk) {
        int ci0 = chunk * CI_CHUNK;
        __syncthreads();
        // weights: w_s[ci][tap][co] <- g_Wt[tap][ci0+ci][co], vectorized, coalesced
        for (int e = tid; e < CI_CHUNK * 9 * 32; e += 256) {
            int v4 = e & 31;
            int ct = e >> 5;            // ci*9+tap
            int ci = ct / 9;
            int tap = ct - ci * 9;
            float4 val = *(const float4*)&g_Wt[((size_t)tap * 128 + (ci0 + ci)) * 128 + v4 * 4];
            *(float4*)&w_s[ci][tap][v4 * 4] = val;
        }
        // inputs: 4 rows (row0-1..row0+2 shifted), 66 columns (x=-1..64 shifted), wraps folded here
        for (int e = tid; e < CI_CHUNK * 4 * 66; e += 256) {
            int xx = e % 66;
            int t  = e / 66;
            int ry = t & 3;
            int ci = t >> 2;
            int cglob = (ci0 + ci - vy + 128) & 127;
            int gy = (row0 + ry - 1 + Sy + 64) & 63;
            int gx = (xx - 1 + Sx + 64) & 63;
            in_s[ci][ry][xx] = hp[(size_t)cglob * 4096 + gy * 64 + gx];
        }
        __syncthreads();

#pragma unroll 1
        for (int ci = 0; ci < CI_CHUNK; ++ci) {
            // broadcast input pairs: bc[dy][m] = value at xx = x0 + m (m=0..5)
            unsigned long long bc[3][6];
#pragma unroll
            for (int dy = 0; dy < 3; ++dy) {
                int ry = rl + dy;
                float4 q = *(const float4*)&in_s[ci][ry][x0];
                bc[dy][0] = bcast2(q.x);
                bc[dy][1] = bcast2(q.y);
                bc[dy][2] = bcast2(q.z);
                bc[dy][3] = bcast2(q.w);
                bc[dy][4] = bcast2(in_s[ci][ry][x0 + 4]);
                bc[dy][5] = bcast2(in_s[ci][ry][x0 + 5]);
            }
#pragma unroll
            for (int tap = 0; tap < 9; ++tap) {
                int dy = tap / 3;
                int dx = tap % 3;
                const ulonglong2* wp = (const ulonglong2*)&w_s[ci][tap][cg * 16];
                ulonglong2 wA = wp[0];
                ulonglong2 wB = wp[1];
                ulonglong2 wC = wp[2];
                ulonglong2 wD = wp[3];
#pragma unroll
                for (int k = 0; k < 4; ++k) {
                    unsigned long long bcv = bc[dy][k + dx];
                    ffma2(acc[0][k], wA.x, bcv);
                    ffma2(acc[1][k], wA.y, bcv);
                    ffma2(acc[2][k], wB.x, bcv);
                    ffma2(acc[3][k], wB.y, bcv);
                    ffma2(acc[4][k], wC.x, bcv);
                    ffma2(acc[5][k], wC.y, bcv);
                    ffma2(acc[6][k], wD.x, bcv);
                    ffma2(acc[7][k], wD.y, bcv);
                }
            }
        }
    }

    // epilogue: + u_full (top-left 32x32 window only), relu, store
    int row = row0 + rl;
    bool do_u = (row < WIN) && (x0 < WIN);
    float* op = out + (size_t)(b * VV + v) * CC * 4096 + row * 64 + x0;
    const float* ub = g_uconv + (size_t)b * CC * 1024 + row * 32 + x0;

#pragma unroll
    for (int j = 0; j < 8; ++j) {
        int co0 = cg * 16 + 2 * j;
        float lo[4], hi[4];
#pragma unroll
        for (int k = 0; k < 4; ++k) {
            unsigned int l, h;
            asm("mov.b64 {%0, %1}, %2;" : "=r"(l), "=r"(h) : "l"(acc[j][k]));
            lo[k] = __uint_as_float(l);
            hi[k] = __uint_as_float(h);
        }
        if (do_u) {
            float4 u0 = *(const float4*)&ub[(size_t)co0 * 1024];
            float4 u1 = *(const float4*)&ub[(size_t)(co0 + 1) * 1024];
            lo[0] += u0.x; lo[1] += u0.y; lo[2] += u0.z; lo[3] += u0.w;
            hi[0] += u1.x; hi[1] += u1.y; hi[2] += u1.z; hi[3] += u1.w;
        }
        float4 r0 = {fmaxf(lo[0], 0.f), fmaxf(lo[1], 0.f), fmaxf(lo[2], 0.f), fmaxf(lo[3], 0.f)};
        float4 r1 = {fmaxf(hi[0], 0.f), fmaxf(hi[1], 0.f), fmaxf(hi[2], 0.f), fmaxf(hi[3], 0.f)};
        *(float4*)&op[(size_t)co0 * 4096] = r0;
        *(float4*)&op[(size_t)(co0 + 1) * 4096] = r1;
    }
}

extern "C" void kernel_launch(void* const* d_in, const int* in_sizes, int n_in,
                              void* d_out, int out_size) {
    const float* u_t    = (const float*)d_in[0];
    const float* h_prev = (const float*)d_in[1];
    const int*   action = (const int*)d_in[2];
    const float* W_u    = (const float*)d_in[3];
    const float* W_h    = (const float*)d_in[4];
    float* out = (float*)d_out;

    transpose_wh_kernel<<<(9 * 128 * 128 + 255) / 256, 256>>>(W_h);
    encoder_kernel<<<dim3(128, 16), 256>>>(u_t, W_u);
    fernn_main_kernel<<<dim3(32, 9, 16), 256>>>(h_prev, action, out);
}

// round 4
// speedup vs baseline: 1.0002x; 1.0002x over previous
#include <cuda_runtime.h>
#include <cstdint>

// Problem constants
// u_t    [16,3,32,32]  f32   d_in[0]
// h_prev [16,9,128,64,64] f32 d_in[1]
// action [16,2] int32         d_in[2]
// W_u    [128,3,3,3] f32      d_in[3]
// W_h    [128,128,3,3] f32    d_in[4]
// out    [16,9,128,64,64] f32
#define WORLD 64
#define WIN   32
#define CC    128
#define BB    16
#define VV    9
#define CI_CHUNK 8

// Scratch (device globals; allocation inside kernel_launch is forbidden)
__device__ float g_Wt[9 * 128 * 128];              // [tap][ci][co]
__device__ float g_uconv[16 * 128 * 32 * 32];      // [b][co][y][x]

// ---------- packed f32x2 helpers ----------
__device__ __forceinline__ unsigned long long bcast2(float v) {
    unsigned long long r;
    unsigned int u = __float_as_uint(v);
    asm("mov.b64 %0, {%1, %2};" : "=l"(r) : "r"(u), "r"(u));
    return r;
}
__device__ __forceinline__ void ffma2(unsigned long long& a,
                                      unsigned long long w,
                                      unsigned long long b) {
    asm("fma.rn.f32x2 %0, %1, %2, %0;" : "+l"(a) : "l"(w), "l"(b));
}

// ---------- W_h transpose: [co][ci][tap] -> [tap][ci][co] ----------
__global__ void transpose_wh_kernel(const float* __restrict__ W_h) {
    int idx = blockIdx.x * blockDim.x + threadIdx.x;
    if (idx >= 9 * 128 * 128) return;
    int co  = idx & 127;
    int ci  = (idx >> 7) & 127;
    int tap = idx >> 14;
    g_Wt[idx] = W_h[(co * 128 + ci) * 9 + tap];
}

// ---------- encoder: circular conv u_t * W_u -> g_uconv ----------
__global__ void encoder_kernel(const float* __restrict__ u_t,
                               const float* __restrict__ W_u) {
    int co = blockIdx.x;
    int b  = blockIdx.y;
    __shared__ float us[3 * 32 * 32];
    __shared__ float ws[27];
    int tid = threadIdx.x;
    const float* up = u_t + (size_t)b * 3 * 1024;
    for (int e = tid; e < 3072; e += 256) us[e] = up[e];
    if (tid < 27) ws[tid] = W_u[co * 27 + tid];
    __syncthreads();

    int y  = (tid * 4) >> 5;
    int x0 = (tid * 4) & 31;
    float acc[4] = {0.f, 0.f, 0.f, 0.f};
#pragma unroll
    for (int ci = 0; ci < 3; ++ci)
#pragma unroll
        for (int ky = 0; ky < 3; ++ky) {
            int yy = (y + ky - 1 + 32) & 31;
#pragma unroll
            for (int kx = 0; kx < 3; ++kx) {
                float w = ws[ci * 9 + ky * 3 + kx];
#pragma unroll
                for (int k = 0; k < 4; ++k) {
                    int xx = (x0 + k + kx - 1 + 32) & 31;
                    acc[k] = fmaf(w, us[ci * 1024 + yy * 32 + xx], acc[k]);
                }
            }
        }
    float4 r = {acc[0], acc[1], acc[2], acc[3]};
    *(float4*)&g_uconv[((size_t)(b * 128 + co) * 32 + y) * 32 + x0] = r;
}

// ---------- main recurrent conv ----------
// Block: one (b, v), 2 output rows. Threads 256: tid = cg*32 + pxg;
// cg (0..7) selects 16 output channels; pxg -> (row_local, x0=4*xg).
// Per thread: 8 co-pairs x 4 px f32x2 accumulators.
__global__ __launch_bounds__(256)
void fernn_main_kernel(const float* __restrict__ h_prev,
                       const int* __restrict__ action,
                       float* __restrict__ out) {
    __shared__ float w_s[CI_CHUNK][9][128];   // [ci][tap][co]
    __shared__ float in_s[CI_CHUNK][4][72];   // [ci][ry][xx], xx-1 = pixel x offset

    int rt = blockIdx.x;   // 0..31 row-pair tile
    int v  = blockIdx.y;   // 0..8
    int b  = blockIdx.z;   // 0..15
    int row0 = rt * 2;

    int tid = threadIdx.x;
    int cg  = tid >> 5;          // 0..7
    int pxg = tid & 31;
    int rl  = pxg >> 4;          // 0..1
    int x0  = (pxg & 15) * 4;    // 0..60

    int ax = action[b * 2 + 0];
    int ay = action[b * 2 + 1];
    int vx = v / 3 - 1;
    int vy = v % 3 - 1;
    // reference (code, not comment!): input = h_prev[b,v,(ci-vy)%C,(y+ky-1+ay-vx)%H,(x+kx-1+ax)%W]
    int Sy = ay - vx;
    int Sx = ax;

    const float* hp = h_prev + (size_t)(b * VV + v) * CC * WORLD * WORLD;

    unsigned long long acc[8][4];
#pragma unroll
    for (int j = 0; j < 8; ++j)
#pragma unroll
        for (int k = 0; k < 4; ++k) acc[j][k] = 0ull;

#pragma unroll 1
    for (int chunk = 0; chunk < CC / CI_CHUNK; ++chunk) {
        int ci0 = chunk * CI_CHUNK;
        __syncthreads();
        // weights: w_s[ci][tap][co] <- g_Wt[tap][ci0+ci][co], vectorized, coalesced
        for (int e = tid; e < CI_CHUNK * 9 * 32; e += 256) {
            int v4 = e & 31;
            int ct = e >> 5;            // ci*9+tap
            int ci = ct / 9;
            int tap = ct - ci * 9;
            float4 val = *(const float4*)&g_Wt[((size_t)tap * 128 + (ci0 + ci)) * 128 + v4 * 4];
            *(float4*)&w_s[ci][tap][v4 * 4] = val;
        }
        // inputs: 4 rows (row0-1..row0+2 shifted), 66 columns (x=-1..64 shifted), wraps folded here
        for (int e = tid; e < CI_CHUNK * 4 * 66; e += 256) {
            int xx = e % 66;
            int t  = e / 66;
            int ry = t & 3;
            int ci = t >> 2;
            int cglob = (ci0 + ci - vy + 128) & 127;
            int gy = (row0 + ry - 1 + Sy + 64) & 63;
            int gx = (xx - 1 + Sx + 64) & 63;
            in_s[ci][ry][xx] = hp[(size_t)cglob * 4096 + gy * 64 + gx];
        }
        __syncthreads();

#pragma unroll 1
        for (int ci = 0; ci < CI_CHUNK; ++ci) {
            // broadcast input pairs: bc[dy][m] = value at xx = x0 + m (m=0..5)
            unsigned long long bc[3][6];
#pragma unroll
            for (int dy = 0; dy < 3; ++dy) {
                int ry = rl + dy;
                float4 q = *(const float4*)&in_s[ci][ry][x0];
                bc[dy][0] = bcast2(q.x);
                bc[dy][1] = bcast2(q.y);
                bc[dy][2] = bcast2(q.z);
                bc[dy][3] = bcast2(q.w);
                bc[dy][4] = bcast2(in_s[ci][ry][x0 + 4]);
                bc[dy][5] = bcast2(in_s[ci][ry][x0 + 5]);
            }
#pragma unroll
            for (int tap = 0; tap < 9; ++tap) {
                int dy = tap / 3;
                int dx = tap % 3;
                const ulonglong2* wp = (const ulonglong2*)&w_s[ci][tap][cg * 16];
                ulonglong2 wA = wp[0];
                ulonglong2 wB = wp[1];
                ulonglong2 wC = wp[2];
                ulonglong2 wD = wp[3];
#pragma unroll
                for (int k = 0; k < 4; ++k) {
                    unsigned long long bcv = bc[dy][k + dx];
                    ffma2(acc[0][k], wA.x, bcv);
                    ffma2(acc[1][k], wA.y, bcv);
                    ffma2(acc[2][k], wB.x, bcv);
                    ffma2(acc[3][k], wB.y, bcv);
                    ffma2(acc[4][k], wC.x, bcv);
                    ffma2(acc[5][k], wC.y, bcv);
                    ffma2(acc[6][k], wD.x, bcv);
                    ffma2(acc[7][k], wD.y, bcv);
                }
            }
        }
    }

    // epilogue: + u_full (top-left 32x32 window only), relu, store
    int row = row0 + rl;
    bool do_u = (row < WIN) && (x0 < WIN);
    float* op = out + (size_t)(b * VV + v) * CC * 4096 + row * 64 + x0;
    const float* ub = g_uconv + (size_t)b * CC * 1024 + row * 32 + x0;

#pragma unroll
    for (int j = 0; j < 8; ++j) {
        int co0 = cg * 16 + 2 * j;
        float lo[4], hi[4];
#pragma unroll
        for (int k = 0; k < 4; ++k) {
            unsigned int l, h;
            asm("mov.b64 {%0, %1}, %2;" : "=r"(l), "=r"(h) : "l"(acc[j][k]));
            lo[k] = __uint_as_float(l);
            hi[k] = __uint_as_float(h);
        }
        if (do_u) {
            float4 u0 = *(const float4*)&ub[(size_t)co0 * 1024];
            float4 u1 = *(const float4*)&ub[(size_t)(co0 + 1) * 1024];
            lo[0] += u0.x; lo[1] += u0.y; lo[2] += u0.z; lo[3] += u0.w;
            hi[0] += u1.x; hi[1] += u1.y; hi[2] += u1.z; hi[3] += u1.w;
        }
        float4 r0 = {fmaxf(lo[0], 0.f), fmaxf(lo[1], 0.f), fmaxf(lo[2], 0.f), fmaxf(lo[3], 0.f)};
        float4 r1 = {fmaxf(hi[0], 0.f), fmaxf(hi[1], 0.f), fmaxf(hi[2], 0.f), fmaxf(hi[3], 0.f)};
        *(float4*)&op[(size_t)co0 * 4096] = r0;
        *(float4*)&op[(size_t)(co0 + 1) * 4096] = r1;
    }
}

extern "C" void kernel_launch(void* const* d_in, const int* in_sizes, int n_in,
                              void* d_out, int out_size) {
    const float* u_t    = (const float*)d_in[0];
    const float* h_prev = (const float*)d_in[1];
    const int*   action = (const int*)d_in[2];
    const float* W_u    = (const float*)d_in[3];
    const float* W_h    = (const float*)d_in[4];
    float* out = (float*)d_out;

    transpose_wh_kernel<<<(9 * 128 * 128 + 255) / 256, 256>>>(W_h);
    encoder_kernel<<<dim3(128, 16), 256>>>(u_t, W_u);
    fernn_main_kernel<<<dim3(32, 9, 16), 256>>>(h_prev, action, out);
}